// round 1
// baseline (speedup 1.0000x reference)
#include <cuda_runtime.h>
#include <cstdint>

// Problem constants
#define BATCH   16
#define TLEN    4096
#define KW      15
#define PAD     7

// Tiling
#define TT      256     // time tile per CTA
#define TTH     8       // t positions per thread
#define NTHREADS 256    // 8 oc * 32 t-subtiles

// ---------------------------------------------------------------------------
// Intermediate activation buffers (static device globals; no runtime alloc)
// ---------------------------------------------------------------------------
__device__ float g_h1[(size_t)BATCH * 512 * TLEN];  // leaf out   128 MiB
__device__ float g_h2[(size_t)BATCH * 256 * TLEN];  // int0 out    64 MiB
__device__ float g_h3[(size_t)BATCH * 256 * TLEN];  // br out      64 MiB
__device__ float g_h4[(size_t)BATCH * 128 * TLEN];  // int1 out    32 MiB
__device__ float g_h5[(size_t)BATCH *  64 * TLEN];  // int2 out    16 MiB
__device__ float g_h6[(size_t)BATCH *  32 * TLEN];  // int3 out     8 MiB
__device__ float g_h7[(size_t)BATCH *  16 * TLEN];  // int4 out     4 MiB

// ---------------------------------------------------------------------------
// Generic grouped conv1d, K=15, SAME padding, optional input concat from two
// sources (for the 'br' layer), bias + optional leaky-relu epilogue.
//
// Grid: (TLEN/TT, groups, BATCH).  Block: 256 threads = 8 oc * 32 t-subtiles.
// Thread (oc, tt) computes out[b][g*COUT+oc][t0 + tt*8 .. +7].
// ---------------------------------------------------------------------------
template<int CIN, int C0, int COUT, bool ACT>
__global__ __launch_bounds__(NTHREADS)
void gconv_kernel(const float* __restrict__ in0, long long bs0,
                  const float* __restrict__ in1, long long bs1,
                  const float* __restrict__ W,
                  const float* __restrict__ bias,
                  float* __restrict__ out, int G)
{
    // shared: input tile with halo, weights (row-padded for bank spread), bias
    __shared__ float sx[CIN][TT + 16];              // need TT+14, pad to +16
    __shared__ float sw[COUT][CIN * KW + 1];        // +1: distinct banks per oc
    __shared__ float sb[COUT];

    const int b  = blockIdx.z;
    const int g  = blockIdx.y;
    const int t0 = blockIdx.x * TT;
    const int tid = threadIdx.x;

    // ---- load weights for this group (contiguous COUT*CIN*KW block) ----
    {
        const float* wsrc = W + (long long)g * COUT * CIN * KW;
        for (int i = tid; i < COUT * CIN * KW; i += NTHREADS) {
            int oc = i / (CIN * KW);
            int r  = i - oc * (CIN * KW);
            sw[oc][r] = wsrc[i];
        }
        if (tid < COUT) sb[tid] = bias[g * COUT + tid];
    }

    // ---- load input tile [t0-7, t0+TT+7) for all CIN channels ----
    for (int idx = tid; idx < CIN * (TT + 14); idx += NTHREADS) {
        int ci = idx / (TT + 14);
        int tl = idx - ci * (TT + 14);
        int t  = t0 + tl - PAD;
        const float* src;
        if (C0 == CIN || ci < C0)
            src = in0 + (long long)b * bs0 + (long long)(g * C0 + ci) * TLEN;
        else
            src = in1 + (long long)b * bs1 + (long long)(g * (CIN - C0) + (ci - C0)) * TLEN;
        sx[ci][tl] = (t >= 0 && t < TLEN) ? src[t] : 0.0f;
    }
    __syncthreads();

    // ---- compute ----
    const int oc = tid & (COUT - 1);   // lane-minor: 8 oc per 8 lanes
    const int tt = tid >> 3;           // 0..31
    const int base = tt * TTH;

    float acc[TTH];
#pragma unroll
    for (int j = 0; j < TTH; j++) acc[j] = 0.0f;

    const float* wrow = &sw[oc][0];

#pragma unroll 1
    for (int ci = 0; ci < CIN; ci++) {
        float xr[TTH + KW - 1];   // 22-wide sliding window
#pragma unroll
        for (int i = 0; i < TTH + KW - 1; i++) xr[i] = sx[ci][base + i];
#pragma unroll
        for (int k = 0; k < KW; k++) {
            float w = wrow[ci * KW + k];
#pragma unroll
            for (int j = 0; j < TTH; j++)
                acc[j] = fmaf(w, xr[j + k], acc[j]);
        }
    }

    // ---- epilogue: bias + leaky relu, write out ----
    const float bv = sb[oc];
    float* dst = out + (((long long)b * G + g) * COUT + oc) * TLEN + t0 + base;
#pragma unroll
    for (int j = 0; j < TTH; j++) {
        float v = acc[j] + bv;
        if (ACT) v = (v > 0.0f) ? v : 0.01f * v;
        dst[j] = v;
    }
}

// ---------------------------------------------------------------------------
// Root: 1x1 conv over 16 channels -> 1 channel (no activation)
// ---------------------------------------------------------------------------
__global__ void root_kernel(const float* __restrict__ h,
                            const float* __restrict__ w,
                            const float* __restrict__ bias,
                            float* __restrict__ out)
{
    int idx = blockIdx.x * blockDim.x + threadIdx.x;   // over BATCH*TLEN
    if (idx >= BATCH * TLEN) return;
    int b = idx / TLEN;
    int t = idx - b * TLEN;
    const float* hp = h + (long long)b * 16 * TLEN + t;
    float s = bias[0];
#pragma unroll
    for (int c = 0; c < 16; c++)
        s = fmaf(__ldg(&w[c]), hp[(long long)c * TLEN], s);
    out[idx] = s;
}

// ---------------------------------------------------------------------------
// Launch
// ---------------------------------------------------------------------------
extern "C" void kernel_launch(void* const* d_in, const int* in_sizes, int n_in,
                              void* d_out, int out_size)
{
    const float* x      = (const float*)d_in[0];
    const float* W_leaf = (const float*)d_in[1];
    const float* b_leaf = (const float*)d_in[2];
    const float* W_int0 = (const float*)d_in[3];
    const float* b_int0 = (const float*)d_in[4];
    const float* W_br   = (const float*)d_in[5];
    const float* b_br   = (const float*)d_in[6];
    const float* W_int1 = (const float*)d_in[7];
    const float* b_int1 = (const float*)d_in[8];
    const float* W_int2 = (const float*)d_in[9];
    const float* b_int2 = (const float*)d_in[10];
    const float* W_int3 = (const float*)d_in[11];
    const float* b_int3 = (const float*)d_in[12];
    const float* W_int4 = (const float*)d_in[13];
    const float* b_int4 = (const float*)d_in[14];
    const float* W_root = (const float*)d_in[15];
    const float* b_root = (const float*)d_in[16];
    float* out = (float*)d_out;

    float *h1, *h2, *h3, *h4, *h5, *h6, *h7;
    cudaGetSymbolAddress((void**)&h1, g_h1);
    cudaGetSymbolAddress((void**)&h2, g_h2);
    cudaGetSymbolAddress((void**)&h3, g_h3);
    cudaGetSymbolAddress((void**)&h4, g_h4);
    cudaGetSymbolAddress((void**)&h5, g_h5);
    cudaGetSymbolAddress((void**)&h6, g_h6);
    cudaGetSymbolAddress((void**)&h7, g_h7);

    const int TB = TLEN / TT;   // 16 tiles along T
    const long long BSX = (long long)1536 * TLEN;

    // 1. leaf: 64 groups, 20 in/group, 8 out/group
    gconv_kernel<20, 20, 8, true><<<dim3(TB, 64, BATCH), NTHREADS>>>(
        x, BSX, nullptr, 0, W_leaf, b_leaf, h1, 64);

    // 2. int0: 32 groups, 16 in/group (from 512 ch)
    gconv_kernel<16, 16, 8, true><<<dim3(TB, 32, BATCH), NTHREADS>>>(
        h1, (long long)512 * TLEN, nullptr, 0, W_int0, b_int0, h2, 32);

    // 3. br: 32 groups, in/group = 8 (h2) + 8 (syn = x channels 1280..1535)
    gconv_kernel<16, 8, 8, true><<<dim3(TB, 32, BATCH), NTHREADS>>>(
        h2, (long long)256 * TLEN,
        x + (long long)1280 * TLEN, BSX,
        W_br, b_br, h3, 32);

    // 4. int1: 16 groups (256 -> 128)
    gconv_kernel<16, 16, 8, true><<<dim3(TB, 16, BATCH), NTHREADS>>>(
        h3, (long long)256 * TLEN, nullptr, 0, W_int1, b_int1, h4, 16);

    // 5. int2: 8 groups (128 -> 64)
    gconv_kernel<16, 16, 8, true><<<dim3(TB, 8, BATCH), NTHREADS>>>(
        h4, (long long)128 * TLEN, nullptr, 0, W_int2, b_int2, h5, 8);

    // 6. int3: 4 groups (64 -> 32)
    gconv_kernel<16, 16, 8, true><<<dim3(TB, 4, BATCH), NTHREADS>>>(
        h5, (long long)64 * TLEN, nullptr, 0, W_int3, b_int3, h6, 4);

    // 7. int4: 2 groups (32 -> 16)
    gconv_kernel<16, 16, 8, true><<<dim3(TB, 2, BATCH), NTHREADS>>>(
        h6, (long long)32 * TLEN, nullptr, 0, W_int4, b_int4, h7, 2);

    // 8. root: 1x1 conv 16 -> 1
    root_kernel<<<(BATCH * TLEN + 255) / 256, 256>>>(h7, W_root, b_root, out);
}

// round 2
// speedup vs baseline: 1.0629x; 1.0629x over previous
#include <cuda_runtime.h>
#include <cstdint>

// Problem constants
#define BATCH   16
#define TLEN    4096
#define KW      15
#define PAD     7

// Tiling
#define TT      512     // time tile per CTA
#define TTH     16      // t positions per thread (8 packed pairs)
#define NTHREADS 256    // 8 oc * 32 t-subtiles

typedef unsigned long long u64;

// ---------------------------------------------------------------------------
// Intermediate activation buffers (static device globals; no runtime alloc)
// ---------------------------------------------------------------------------
__device__ float g_h1[(size_t)BATCH * 512 * TLEN];  // leaf out   128 MiB
__device__ float g_h2[(size_t)BATCH * 256 * TLEN];  // int0 out    64 MiB
__device__ float g_h3[(size_t)BATCH * 256 * TLEN];  // br out      64 MiB
__device__ float g_h4[(size_t)BATCH * 128 * TLEN];  // int1 out    32 MiB
__device__ float g_h5[(size_t)BATCH *  64 * TLEN];  // int2 out    16 MiB
__device__ float g_h6[(size_t)BATCH *  32 * TLEN];  // int3 out     8 MiB
__device__ float g_h7[(size_t)BATCH *  16 * TLEN];  // int4 out     4 MiB

// ---------------------------------------------------------------------------
// Packed f32x2 helpers (FFMA2 is only reachable via PTX)
// ---------------------------------------------------------------------------
__device__ __forceinline__ u64 pack2(float lo, float hi) {
    u64 r; asm("mov.b64 %0,{%1,%2};" : "=l"(r) : "f"(lo), "f"(hi)); return r;
}
__device__ __forceinline__ void unpack2(u64 v, float& lo, float& hi) {
    asm("mov.b64 {%0,%1},%2;" : "=f"(lo), "=f"(hi) : "l"(v));
}
__device__ __forceinline__ u64 ffma2(u64 a, u64 b, u64 c) {
    u64 d; asm("fma.rn.f32x2 %0,%1,%2,%3;" : "=l"(d) : "l"(a), "l"(b), "l"(c));
    return d;
}
// returns {hi(a), lo(b)} — the odd-aligned pair
__device__ __forceinline__ u64 shiftpair(u64 a, u64 b) {
    u64 r;
    asm("{\n\t.reg .f32 al,ah,bl,bh;\n\t"
        "mov.b64 {al,ah},%1;\n\t"
        "mov.b64 {bl,bh},%2;\n\t"
        "mov.b64 %0,{ah,bl};\n\t}"
        : "=l"(r) : "l"(a), "l"(b));
    return r;
}

// ---------------------------------------------------------------------------
// Grouped conv1d, K=15, SAME padding, packed-f32x2 inner loop.
// Grid: (TLEN/TT, groups, BATCH).  Block: 256 = 8 oc * 32 t-subtiles.
// Thread (oc, tt) computes out[b][g*COUT+oc][t0 + tt*16 .. +15].
// Dynamic smem layout: [ sw2: COUT*(CIN*KW+1) u64 | sx: CIN*(TT+16) f32 | sb: COUT f32 ]
// ---------------------------------------------------------------------------
template<int CIN, int C0, int COUT, bool ACT>
__global__ __launch_bounds__(NTHREADS)
void gconv_kernel(const float* __restrict__ in0, long long bs0,
                  const float* __restrict__ in1, long long bs1,
                  const float* __restrict__ W,
                  const float* __restrict__ bias,
                  float* __restrict__ out, int G)
{
    extern __shared__ char smem_raw[];
    const int WROW = CIN * KW + 1;          // +1 u64: spread oc rows across banks
    const int XROW = TT + 16;               // need TT+14, pad to +16 (keeps 8B align)
    u64*   sw2 = (u64*)smem_raw;            // packed (w,w) weights
    float* sx  = (float*)(sw2 + COUT * WROW);
    float* sb  = sx + CIN * XROW;

    const int b   = blockIdx.z;
    const int g   = blockIdx.y;
    const int t0  = blockIdx.x * TT;
    const int tid = threadIdx.x;

    // ---- stage packed weights for this group ----
    {
        const float* wsrc = W + (long long)g * COUT * CIN * KW;
        for (int i = tid; i < COUT * CIN * KW; i += NTHREADS) {
            int oc = i / (CIN * KW);
            int r  = i - oc * (CIN * KW);
            float w = wsrc[i];
            sw2[oc * WROW + r] = pack2(w, w);
        }
        if (tid < COUT) sb[tid] = bias[g * COUT + tid];
    }

    // ---- stage input tile [t0-7, t0+TT+7) for all CIN channels ----
    for (int idx = tid; idx < CIN * XROW; idx += NTHREADS) {
        int ci = idx / XROW;
        int tl = idx - ci * XROW;
        int t  = t0 + tl - PAD;
        const float* src;
        if (C0 == CIN || ci < C0)
            src = in0 + (long long)b * bs0 + (long long)(g * C0 + ci) * TLEN;
        else
            src = in1 + (long long)b * bs1 + (long long)(g * (CIN - C0) + (ci - C0)) * TLEN;
        sx[ci * XROW + tl] = (t >= 0 && t < TLEN) ? src[t] : 0.0f;
    }
    __syncthreads();

    // ---- compute ----
    const int oc   = tid & (COUT - 1);      // oc lane-minor (broadcast-friendly)
    const int tt   = tid >> 3;              // 0..31
    const int base = tt * TTH;              // 64B-aligned window start

    u64 acc[8];
#pragma unroll
    for (int j = 0; j < 8; j++) acc[j] = 0ull;   // packed (+0.0f, +0.0f)

    const u64*   wrow  = sw2 + oc * WROW;
    const float* xbase = sx + base;

#pragma unroll 1
    for (int ci = 0; ci < CIN; ci++) {
        // even-aligned packed window: pe[i] = (x[2i], x[2i+1]), i=0..14 -> x[0..29]
        u64 pe[15];
        const u64* xp = (const u64*)(xbase + ci * XROW);
#pragma unroll
        for (int i = 0; i < 15; i++) pe[i] = xp[i];
        // odd-aligned packed window: po[i] = (x[2i+1], x[2i+2]), i=0..13
        u64 po[14];
#pragma unroll
        for (int i = 0; i < 14; i++) po[i] = shiftpair(pe[i], pe[i + 1]);

        const u64* wp = wrow + ci * KW;
#pragma unroll
        for (int k = 0; k < KW; k++) {
            u64 w2 = wp[k];
            int m = k >> 1;
            if ((k & 1) == 0) {
#pragma unroll
                for (int j = 0; j < 8; j++) acc[j] = ffma2(pe[m + j], w2, acc[j]);
            } else {
#pragma unroll
                for (int j = 0; j < 8; j++) acc[j] = ffma2(po[m + j], w2, acc[j]);
            }
        }
    }

    // ---- epilogue: bias + leaky relu, vectorized store ----
    const float bv = sb[oc];
    float res[TTH];
#pragma unroll
    for (int j = 0; j < 8; j++) {
        float lo, hi;
        unpack2(acc[j], lo, hi);
        lo += bv; hi += bv;
        if (ACT) { lo = lo > 0.0f ? lo : 0.01f * lo; hi = hi > 0.0f ? hi : 0.01f * hi; }
        res[2 * j] = lo; res[2 * j + 1] = hi;
    }
    float* dst = out + (((long long)b * G + g) * COUT + oc) * TLEN + t0 + base;
#pragma unroll
    for (int j = 0; j < 4; j++)
        ((float4*)dst)[j] = make_float4(res[4*j], res[4*j+1], res[4*j+2], res[4*j+3]);
}

// ---------------------------------------------------------------------------
// Root: 1x1 conv over 16 channels -> 1 channel (no activation)
// ---------------------------------------------------------------------------
__global__ void root_kernel(const float* __restrict__ h,
                            const float* __restrict__ w,
                            const float* __restrict__ bias,
                            float* __restrict__ out)
{
    int idx = blockIdx.x * blockDim.x + threadIdx.x;   // over BATCH*TLEN
    if (idx >= BATCH * TLEN) return;
    int b = idx / TLEN;
    int t = idx - b * TLEN;
    const float* hp = h + (long long)b * 16 * TLEN + t;
    float s = bias[0];
#pragma unroll
    for (int c = 0; c < 16; c++)
        s = fmaf(__ldg(&w[c]), hp[(long long)c * TLEN], s);
    out[idx] = s;
}

// ---------------------------------------------------------------------------
// Launch
// ---------------------------------------------------------------------------
static inline int smem_bytes(int cin, int cout) {
    return cout * (cin * KW + 1) * 8 + cin * (TT + 16) * 4 + cout * 4;
}

extern "C" void kernel_launch(void* const* d_in, const int* in_sizes, int n_in,
                              void* d_out, int out_size)
{
    const float* x      = (const float*)d_in[0];
    const float* W_leaf = (const float*)d_in[1];
    const float* b_leaf = (const float*)d_in[2];
    const float* W_int0 = (const float*)d_in[3];
    const float* b_int0 = (const float*)d_in[4];
    const float* W_br   = (const float*)d_in[5];
    const float* b_br   = (const float*)d_in[6];
    const float* W_int1 = (const float*)d_in[7];
    const float* b_int1 = (const float*)d_in[8];
    const float* W_int2 = (const float*)d_in[9];
    const float* b_int2 = (const float*)d_in[10];
    const float* W_int3 = (const float*)d_in[11];
    const float* b_int3 = (const float*)d_in[12];
    const float* W_int4 = (const float*)d_in[13];
    const float* b_int4 = (const float*)d_in[14];
    const float* W_root = (const float*)d_in[15];
    const float* b_root = (const float*)d_in[16];
    float* out = (float*)d_out;

    float *h1, *h2, *h3, *h4, *h5, *h6, *h7;
    cudaGetSymbolAddress((void**)&h1, g_h1);
    cudaGetSymbolAddress((void**)&h2, g_h2);
    cudaGetSymbolAddress((void**)&h3, g_h3);
    cudaGetSymbolAddress((void**)&h4, g_h4);
    cudaGetSymbolAddress((void**)&h5, g_h5);
    cudaGetSymbolAddress((void**)&h6, g_h6);
    cudaGetSymbolAddress((void**)&h7, g_h7);

    const int TB = TLEN / TT;   // 8 tiles along T
    const long long BSX = (long long)1536 * TLEN;

    const int SM20 = smem_bytes(20, 8);
    const int SM16 = smem_bytes(16, 8);

    cudaFuncSetAttribute(gconv_kernel<20, 20, 8, true>,
                         cudaFuncAttributeMaxDynamicSharedMemorySize, SM20);
    cudaFuncSetAttribute(gconv_kernel<16, 16, 8, true>,
                         cudaFuncAttributeMaxDynamicSharedMemorySize, SM16);
    cudaFuncSetAttribute(gconv_kernel<16, 8, 8, true>,
                         cudaFuncAttributeMaxDynamicSharedMemorySize, SM16);

    // 1. leaf: 64 groups, 20 in/group, 8 out/group
    gconv_kernel<20, 20, 8, true><<<dim3(TB, 64, BATCH), NTHREADS, SM20>>>(
        x, BSX, nullptr, 0, W_leaf, b_leaf, h1, 64);

    // 2. int0: 32 groups, 16 in/group (from 512 ch)
    gconv_kernel<16, 16, 8, true><<<dim3(TB, 32, BATCH), NTHREADS, SM16>>>(
        h1, (long long)512 * TLEN, nullptr, 0, W_int0, b_int0, h2, 32);

    // 3. br: 32 groups, in/group = 8 (h2) + 8 (syn = x channels 1280..1535)
    gconv_kernel<16, 8, 8, true><<<dim3(TB, 32, BATCH), NTHREADS, SM16>>>(
        h2, (long long)256 * TLEN,
        x + (long long)1280 * TLEN, BSX,
        W_br, b_br, h3, 32);

    // 4. int1: 16 groups (256 -> 128)
    gconv_kernel<16, 16, 8, true><<<dim3(TB, 16, BATCH), NTHREADS, SM16>>>(
        h3, (long long)256 * TLEN, nullptr, 0, W_int1, b_int1, h4, 16);

    // 5. int2: 8 groups (128 -> 64)
    gconv_kernel<16, 16, 8, true><<<dim3(TB, 8, BATCH), NTHREADS, SM16>>>(
        h4, (long long)128 * TLEN, nullptr, 0, W_int2, b_int2, h5, 8);

    // 6. int3: 4 groups (64 -> 32)
    gconv_kernel<16, 16, 8, true><<<dim3(TB, 4, BATCH), NTHREADS, SM16>>>(
        h5, (long long)64 * TLEN, nullptr, 0, W_int3, b_int3, h6, 4);

    // 7. int4: 2 groups (32 -> 16)
    gconv_kernel<16, 16, 8, true><<<dim3(TB, 2, BATCH), NTHREADS, SM16>>>(
        h6, (long long)32 * TLEN, nullptr, 0, W_int4, b_int4, h7, 2);

    // 8. root: 1x1 conv 16 -> 1
    root_kernel<<<(BATCH * TLEN + 255) / 256, 256>>>(h7, W_root, b_root, out);
}